// round 1
// baseline (speedup 1.0000x reference)
#include <cuda_runtime.h>
#include <math.h>

#define BATCH 8
#define SEQ   2048
#define EDIM  1024
#define HDIM  64
#define MTOT  (BATCH*SEQ)          // 16384 rows total

// q/k/v projection scratch (device globals: no allocation allowed)
__device__ float g_q[MTOT*HDIM];
__device__ float g_k[MTOT*HDIM];
__device__ float g_v[MTOT*HDIM];

// ---------------------------------------------------------------------------
// Kernel 1: fused QKV projection.  C[16384,192] = X[16384,1024] @ [Wk|Wq|Wv]
// Block tile: 128 rows x 192 cols, K-chunk 16.  256 threads, 8x12 micro-tile.
// ---------------------------------------------------------------------------
#define PM 128
#define PK 16

__global__ void __launch_bounds__(256) proj_kernel(
    const float* __restrict__ x,
    const float* __restrict__ wk,
    const float* __restrict__ wq,
    const float* __restrict__ wv)
{
    __shared__ float Xs[PM][PK];     // 8 KB
    __shared__ float Ws[PK][192];    // 12 KB  (cols 0-63 Wk, 64-127 Wq, 128-191 Wv)

    const int tid  = threadIdx.x;
    const int tx   = tid & 15;       // 16 col-groups
    const int ty   = tid >> 4;       // 16 row-groups
    const int row0 = blockIdx.x * PM;

    float acc[8][12];
#pragma unroll
    for (int i = 0; i < 8; i++)
#pragma unroll
        for (int j = 0; j < 12; j++) acc[i][j] = 0.f;

    for (int k0 = 0; k0 < EDIM; k0 += PK) {
        // load X tile: 128x16 floats = 512 float4, 2 per thread (coalesced 64B runs)
#pragma unroll
        for (int l = 0; l < 2; l++) {
            int idx = tid + l*256;            // 0..511
            int r   = idx >> 2;
            int c   = (idx & 3) << 2;
            *(float4*)&Xs[r][c] =
                *(const float4*)&x[(size_t)(row0 + r)*EDIM + k0 + c];
        }
        // load W tiles: 16x64 per matrix = 256 float4 each, 1 per thread per matrix
        {
            int r = tid >> 4;                 // 0..15
            int c = (tid & 15) << 2;          // 0..60
            *(float4*)&Ws[r][c]       = *(const float4*)&wk[(k0 + r)*HDIM + c];
            *(float4*)&Ws[r][64 + c]  = *(const float4*)&wq[(k0 + r)*HDIM + c];
            *(float4*)&Ws[r][128 + c] = *(const float4*)&wv[(k0 + r)*HDIM + c];
        }
        __syncthreads();

#pragma unroll
        for (int k = 0; k < PK; k++) {
            float a[8], b[12];
#pragma unroll
            for (int i = 0; i < 8; i++) a[i] = Xs[ty*8 + i][k];
#pragma unroll
            for (int s = 0; s < 3; s++) {
                float4 t = *(float4*)&Ws[k][s*64 + tx*4];
                b[s*4+0] = t.x; b[s*4+1] = t.y; b[s*4+2] = t.z; b[s*4+3] = t.w;
            }
#pragma unroll
            for (int i = 0; i < 8; i++)
#pragma unroll
                for (int j = 0; j < 12; j++)
                    acc[i][j] = fmaf(a[i], b[j], acc[i][j]);
        }
        __syncthreads();
    }

    // epilogue: seg0 -> K, seg1 -> Q, seg2 -> V
#pragma unroll
    for (int i = 0; i < 8; i++) {
        int row = row0 + ty*8 + i;
        *(float4*)&g_k[row*HDIM + tx*4] =
            make_float4(acc[i][0], acc[i][1], acc[i][2],  acc[i][3]);
        *(float4*)&g_q[row*HDIM + tx*4] =
            make_float4(acc[i][4], acc[i][5], acc[i][6],  acc[i][7]);
        *(float4*)&g_v[row*HDIM + tx*4] =
            make_float4(acc[i][8], acc[i][9], acc[i][10], acc[i][11]);
    }
}

// ---------------------------------------------------------------------------
// Kernel 2: causal flash attention, fp32.
// Per block: one 64-row q-tile of one batch.  256 threads = 16x16.
// Thread (ty,tx) owns score/O rows r = ty*4+i, cols c/h = tx + 16*j (strided,
// keeps all shared loads broadcast or conflict-free).
// ---------------------------------------------------------------------------
#define TILE  64
#define PITCH 68   // 64 + 4 pad floats; float4-aligned, kills stride-64 conflicts
#define ATTN_SMEM (4 * TILE * PITCH * (int)sizeof(float))   // 69632 B

__global__ void __launch_bounds__(256) attn_kernel(float* __restrict__ out)
{
    extern __shared__ float sm[];
    float* Qs = sm;
    float* Ks = sm + 1*TILE*PITCH;
    float* Vs = sm + 2*TILE*PITCH;
    float* Ps = sm + 3*TILE*PITCH;

    const int tid = threadIdx.x;
    const int tx  = tid & 15;
    const int ty  = tid >> 4;
    const int qt  = 31 - (int)blockIdx.x;   // heavy (long) q-tiles launch first
    const int b   = blockIdx.y;
    const int q0  = qt * TILE;

    const float* Qg = g_q + (size_t)b*SEQ*HDIM;
    const float* Kg = g_k + (size_t)b*SEQ*HDIM;
    const float* Vg = g_v + (size_t)b*SEQ*HDIM;

    // load Q tile (64x64 = 1024 float4, 4 per thread)
#pragma unroll
    for (int l = 0; l < 4; l++) {
        int idx = tid + l*256;
        int r   = idx >> 4;
        int c   = (idx & 15) << 2;
        *(float4*)&Qs[r*PITCH + c] = *(const float4*)&Qg[(q0 + r)*HDIM + c];
    }

    float m_i[4], l_i[4], o[4][4];
#pragma unroll
    for (int i = 0; i < 4; i++) {
        m_i[i] = -1e30f; l_i[i] = 0.f;
#pragma unroll
        for (int j = 0; j < 4; j++) o[i][j] = 0.f;
    }

    for (int jt = 0; jt <= qt; jt++) {
        const int k0 = jt * TILE;
        __syncthreads();   // previous iter's Ks/Vs/Ps consumption complete
#pragma unroll
        for (int l = 0; l < 4; l++) {
            int idx = tid + l*256;
            int r   = idx >> 4;
            int c   = (idx & 15) << 2;
            *(float4*)&Ks[r*PITCH + c] = *(const float4*)&Kg[(k0 + r)*HDIM + c];
            *(float4*)&Vs[r*PITCH + c] = *(const float4*)&Vg[(k0 + r)*HDIM + c];
        }
        __syncthreads();   // also covers initial Q tile on first iteration

        // scores: s[i][j] = sum_h Q[r][h] * K[c][h]
        float s[4][4];
#pragma unroll
        for (int i = 0; i < 4; i++)
#pragma unroll
            for (int j = 0; j < 4; j++) s[i][j] = 0.f;

        for (int h = 0; h < HDIM; h += 4) {
            float4 a[4], kk[4];
#pragma unroll
            for (int i = 0; i < 4; i++)
                a[i] = *(float4*)&Qs[(ty*4 + i)*PITCH + h];
#pragma unroll
            for (int j = 0; j < 4; j++)
                kk[j] = *(float4*)&Ks[(tx + 16*j)*PITCH + h];
#pragma unroll
            for (int i = 0; i < 4; i++)
#pragma unroll
                for (int j = 0; j < 4; j++) {
                    s[i][j] = fmaf(a[i].x, kk[j].x, s[i][j]);
                    s[i][j] = fmaf(a[i].y, kk[j].y, s[i][j]);
                    s[i][j] = fmaf(a[i].z, kk[j].z, s[i][j]);
                    s[i][j] = fmaf(a[i].w, kk[j].w, s[i][j]);
                }
        }

        // scale + causal mask (diagonal tile only: k0 == q0 -> mask c > r)
        const bool diag = (jt == qt);
#pragma unroll
        for (int i = 0; i < 4; i++)
#pragma unroll
            for (int j = 0; j < 4; j++) {
                float v = s[i][j] * 0.125f;   // H^-0.5 = 1/8
                s[i][j] = (diag && (tx + 16*j) > (ty*4 + i)) ? -1e30f : v;
            }

        // online softmax update (row reductions across the 16 tx lanes)
#pragma unroll
        for (int i = 0; i < 4; i++) {
            float mt = fmaxf(fmaxf(s[i][0], s[i][1]), fmaxf(s[i][2], s[i][3]));
#pragma unroll
            for (int off = 8; off >= 1; off >>= 1)
                mt = fmaxf(mt, __shfl_xor_sync(0xffffffffu, mt, off));
            float mn = fmaxf(m_i[i], mt);
            float al = __expf(m_i[i] - mn);
            float rs = 0.f;
#pragma unroll
            for (int j = 0; j < 4; j++) {
                float p = __expf(s[i][j] - mn);
                Ps[(ty*4 + i)*PITCH + tx + 16*j] = p;
                rs += p;
            }
#pragma unroll
            for (int off = 8; off >= 1; off >>= 1)
                rs += __shfl_xor_sync(0xffffffffu, rs, off);
            l_i[i] = al * l_i[i] + rs;
            m_i[i] = mn;
#pragma unroll
            for (int j = 0; j < 4; j++) o[i][j] *= al;
        }
        __syncthreads();   // P tile visible to all

        // O += P @ V
        for (int c = 0; c < TILE; c += 4) {
            float4 p4[4];
#pragma unroll
            for (int i = 0; i < 4; i++)
                p4[i] = *(float4*)&Ps[(ty*4 + i)*PITCH + c];
            float vv[4][4];
#pragma unroll
            for (int u = 0; u < 4; u++)
#pragma unroll
                for (int j = 0; j < 4; j++)
                    vv[u][j] = Vs[(c + u)*PITCH + tx + 16*j];
#pragma unroll
            for (int i = 0; i < 4; i++)
#pragma unroll
                for (int j = 0; j < 4; j++) {
                    o[i][j] = fmaf(p4[i].x, vv[0][j], o[i][j]);
                    o[i][j] = fmaf(p4[i].y, vv[1][j], o[i][j]);
                    o[i][j] = fmaf(p4[i].z, vv[2][j], o[i][j]);
                    o[i][j] = fmaf(p4[i].w, vv[3][j], o[i][j]);
                }
        }
    }

    // epilogue: normalize and store
#pragma unroll
    for (int i = 0; i < 4; i++) {
        float inv = 1.f / l_i[i];
        int row = b*SEQ + q0 + ty*4 + i;
#pragma unroll
        for (int j = 0; j < 4; j++)
            out[row*HDIM + tx + 16*j] = o[i][j] * inv;
    }
}

// ---------------------------------------------------------------------------
extern "C" void kernel_launch(void* const* d_in, const int* in_sizes, int n_in,
                              void* d_out, int out_size)
{
    const float* x  = (const float*)d_in[0];
    const float* wk = (const float*)d_in[1];
    const float* wq = (const float*)d_in[2];
    const float* wv = (const float*)d_in[3];
    float* out = (float*)d_out;

    proj_kernel<<<MTOT / PM, 256>>>(x, wk, wq, wv);

    cudaFuncSetAttribute(attn_kernel,
                         cudaFuncAttributeMaxDynamicSharedMemorySize, ATTN_SMEM);
    dim3 grid(SEQ / TILE, BATCH);   // (32, 8) = 256 blocks
    attn_kernel<<<grid, 256, ATTN_SMEM>>>(out);
}

// round 2
// speedup vs baseline: 2.5786x; 2.5786x over previous
#include <cuda_runtime.h>
#include <cuda_bf16.h>
#include <math.h>
#include <stdint.h>

#define BATCH 8
#define SEQ   2048
#define EDIM  1024
#define HDIM  64
#define MTOT  (BATCH*SEQ)

// qkv scratch
__device__ float g_q[MTOT*HDIM];
__device__ float g_k[MTOT*HDIM];
__device__ float g_v[MTOT*HDIM];

// ---------------------------------------------------------------------------
// helpers
// ---------------------------------------------------------------------------
__device__ __forceinline__ void mma_bf16(float& d0, float& d1, float& d2, float& d3,
                                         uint32_t a0, uint32_t a1, uint32_t a2, uint32_t a3,
                                         uint32_t b0, uint32_t b1)
{
    asm("mma.sync.aligned.m16n8k16.row.col.f32.bf16.bf16.f32 "
        "{%0,%1,%2,%3},{%4,%5,%6,%7},{%8,%9},{%0,%1,%2,%3};"
        : "+f"(d0), "+f"(d1), "+f"(d2), "+f"(d3)
        : "r"(a0), "r"(a1), "r"(a2), "r"(a3), "r"(b0), "r"(b1));
}

// split x into hi+lo bf16
__device__ __forceinline__ void split2(float x, __nv_bfloat16& h, __nv_bfloat16& l)
{
    h = __float2bfloat16(x);
    l = __float2bfloat16(x - __bfloat162float(h));
}

// pack (x0 -> low half, x1 -> high half) hi/lo pairs
__device__ __forceinline__ void split_pack(float x0, float x1, uint32_t& hp, uint32_t& lp)
{
    __nv_bfloat16 h0, l0, h1, l1;
    split2(x0, h0, l0);
    split2(x1, h1, l1);
    __nv_bfloat162 hh = __halves2bfloat162(h0, h1);
    __nv_bfloat162 ll = __halves2bfloat162(l0, l1);
    hp = *reinterpret_cast<uint32_t*>(&hh);
    lp = *reinterpret_cast<uint32_t*>(&ll);
}

// ---------------------------------------------------------------------------
// Kernel 1: fused QKV projection, HMMA bf16 split.
// Block: 128 rows x 192 cols, 256 thr (8 warps = 2m x 4n), K-chunk 32.
// ---------------------------------------------------------------------------
#define AP 40     // A smem pitch (bf16)
#define BP 196    // B smem pitch (u32 k-pairs)

__global__ void __launch_bounds__(256) proj_kernel(
    const float* __restrict__ x,
    const float* __restrict__ wk,
    const float* __restrict__ wq,
    const float* __restrict__ wv)
{
    __shared__ __nv_bfloat16 Ah[128][AP], Al[128][AP];   // 10240 B each
    __shared__ uint32_t      Bh[16][BP],  Bl[16][BP];    // 12544 B each

    const int tid   = threadIdx.x;
    const int lane  = tid & 31;
    const int warp  = tid >> 5;
    const int warpM = warp >> 2;     // 0..1
    const int warpN = warp & 3;      // 0..3
    const int g     = lane >> 2;     // 0..7
    const int tg    = lane & 3;      // 0..3
    const int row0  = blockIdx.x * 128;

    float acc[4][6][4];
#pragma unroll
    for (int i = 0; i < 4; i++)
#pragma unroll
        for (int j = 0; j < 6; j++)
#pragma unroll
            for (int r = 0; r < 4; r++) acc[i][j][r] = 0.f;

    for (int k0 = 0; k0 < EDIM; k0 += 32) {
        // ---- fill X tile (128x32) ----
#pragma unroll
        for (int l = 0; l < 4; l++) {
            int idx = tid + l * 256;             // 0..1023 float4
            int r   = idx >> 3;
            int c   = (idx & 7) << 2;
            float4 v = *(const float4*)&x[(size_t)(row0 + r) * EDIM + k0 + c];
            __nv_bfloat16 h0,l0,h1,l1,h2,l2,h3,l3;
            split2(v.x, h0, l0); split2(v.y, h1, l1);
            split2(v.z, h2, l2); split2(v.w, h3, l3);
            *(__nv_bfloat162*)&Ah[r][c]     = __halves2bfloat162(h0, h1);
            *(__nv_bfloat162*)&Ah[r][c + 2] = __halves2bfloat162(h2, h3);
            *(__nv_bfloat162*)&Al[r][c]     = __halves2bfloat162(l0, l1);
            *(__nv_bfloat162*)&Al[r][c + 2] = __halves2bfloat162(l2, l3);
        }
        // ---- fill W tile (32x192 -> 16 k-pairs x 192), cols: K|Q|V ----
#pragma unroll
        for (int l = 0; l < 12; l++) {
            int idx = tid + l * 256;             // 0..3071
            int rp  = idx / 192;
            int c   = idx - rp * 192;
            const float* wp = (c < 64) ? wk : ((c < 128) ? wq : wv);
            int cc = c & 63;
            float w0 = wp[(k0 + 2 * rp)     * HDIM + cc];
            float w1 = wp[(k0 + 2 * rp + 1) * HDIM + cc];
            uint32_t hp, lp;
            split_pack(w0, w1, hp, lp);
            Bh[rp][c] = hp;
            Bl[rp][c] = lp;
        }
        __syncthreads();

        const uint32_t* Ah32 = (const uint32_t*)&Ah[0][0];
        const uint32_t* Al32 = (const uint32_t*)&Al[0][0];
        const int ap32 = AP / 2;     // 20

#pragma unroll
        for (int k16 = 0; k16 < 2; k16++) {
            uint32_t ah[4][4], al[4][4];
#pragma unroll
            for (int mt = 0; mt < 4; mt++) {
                int rb = (warpM * 64 + mt * 16 + g) * ap32 + k16 * 8 + tg;
                ah[mt][0] = Ah32[rb];
                ah[mt][1] = Ah32[rb + 8 * ap32];
                ah[mt][2] = Ah32[rb + 4];
                ah[mt][3] = Ah32[rb + 8 * ap32 + 4];
                al[mt][0] = Al32[rb];
                al[mt][1] = Al32[rb + 8 * ap32];
                al[mt][2] = Al32[rb + 4];
                al[mt][3] = Al32[rb + 8 * ap32 + 4];
            }
#pragma unroll
            for (int nt = 0; nt < 6; nt++) {
                int n  = warpN * 48 + nt * 8 + g;
                int kp = k16 * 8 + tg;
                uint32_t bh0 = Bh[kp][n],     bh1 = Bh[kp + 4][n];
                uint32_t bl0 = Bl[kp][n],     bl1 = Bl[kp + 4][n];
#pragma unroll
                for (int mt = 0; mt < 4; mt++) {
                    float* c = acc[mt][nt];
                    mma_bf16(c[0], c[1], c[2], c[3], ah[mt][0], ah[mt][1], ah[mt][2], ah[mt][3], bh0, bh1);
                    mma_bf16(c[0], c[1], c[2], c[3], al[mt][0], al[mt][1], al[mt][2], al[mt][3], bh0, bh1);
                    mma_bf16(c[0], c[1], c[2], c[3], ah[mt][0], ah[mt][1], ah[mt][2], ah[mt][3], bl0, bl1);
                }
            }
        }
        __syncthreads();
    }

    // epilogue
#pragma unroll
    for (int mt = 0; mt < 4; mt++) {
#pragma unroll
        for (int nt = 0; nt < 6; nt++) {
            int gcol = warpN * 48 + nt * 8 + 2 * tg;
            int seg  = gcol >> 6;
            int cc   = gcol & 63;
            float* dst = (seg == 0) ? g_k : ((seg == 1) ? g_q : g_v);
            int r0 = row0 + warpM * 64 + mt * 16 + g;
            float* c = acc[mt][nt];
            *(float2*)&dst[r0 * HDIM + cc]       = make_float2(c[0], c[1]);
            *(float2*)&dst[(r0 + 8) * HDIM + cc] = make_float2(c[2], c[3]);
        }
    }
}

// ---------------------------------------------------------------------------
// Kernel 2: causal flash attention, HMMA bf16 split.
// Block = 128 thr (4 warps), processes q-tile pair (31-p, p): 33 key-tiles.
// Warp owns 16 q-rows. Tiles: q 64, key 64.
// ---------------------------------------------------------------------------
#define QKP 72            // Q/K smem pitch in bf16
#define VPP 68            // V smem pitch in u32 (k-pair packed)
#define ATTN_SMEM (4*64*QKP*2 + 2*32*VPP*4)    // 54272 B

__global__ void __launch_bounds__(128) attn_kernel(float* __restrict__ out)
{
    extern __shared__ unsigned char smraw[];
    __nv_bfloat16* Qh = (__nv_bfloat16*)smraw;
    __nv_bfloat16* Ql = Qh + 64 * QKP;
    __nv_bfloat16* Kh = Ql + 64 * QKP;
    __nv_bfloat16* Kl = Kh + 64 * QKP;
    uint32_t*      Vh = (uint32_t*)(Kl + 64 * QKP);
    uint32_t*      Vl = Vh + 32 * VPP;

    const int tid  = threadIdx.x;
    const int lane = tid & 31;
    const int warp = tid >> 5;     // 0..3
    const int g    = lane >> 2;    // 0..7
    const int tg   = lane & 3;     // 0..3
    const int p    = blockIdx.x;   // 0..15
    const int b    = blockIdx.y;

    const float* Qg = g_q + (size_t)b * SEQ * HDIM;
    const float* Kg = g_k + (size_t)b * SEQ * HDIM;
    const float* Vg = g_v + (size_t)b * SEQ * HDIM;

    const uint32_t* Qh32 = (const uint32_t*)Qh;
    const uint32_t* Ql32 = (const uint32_t*)Ql;
    const uint32_t* Kh32 = (const uint32_t*)Kh;
    const uint32_t* Kl32 = (const uint32_t*)Kl;
    const int qp32 = QKP / 2;   // 36

    const float C = 0.125f * 1.44269504088896340736f;  // scale * log2(e)

#pragma unroll 1
    for (int pass = 0; pass < 2; pass++) {
        const int qt = pass ? p : (31 - p);
        const int q0 = qt * 64;

        __syncthreads();   // previous pass fully consumed smem
        // ---- fill Q tile (64x64), hi/lo ----
#pragma unroll
        for (int l = 0; l < 8; l++) {
            int idx = tid + l * 128;
            int r   = idx >> 4;
            int c   = (idx & 15) << 2;
            float4 v = *(const float4*)&Qg[(q0 + r) * HDIM + c];
            __nv_bfloat16 h0,l0,h1,l1,h2,l2,h3,l3;
            split2(v.x, h0, l0); split2(v.y, h1, l1);
            split2(v.z, h2, l2); split2(v.w, h3, l3);
            *(__nv_bfloat162*)&Qh[r*QKP + c]     = __halves2bfloat162(h0, h1);
            *(__nv_bfloat162*)&Qh[r*QKP + c + 2] = __halves2bfloat162(h2, h3);
            *(__nv_bfloat162*)&Ql[r*QKP + c]     = __halves2bfloat162(l0, l1);
            *(__nv_bfloat162*)&Ql[r*QKP + c + 2] = __halves2bfloat162(l2, l3);
        }
        __syncthreads();

        // ---- preload Q fragments (held in regs for all key tiles) ----
        uint32_t qfh[4][4], qfl[4][4];
        {
            int rowq = warp * 16 + g;
#pragma unroll
            for (int kk = 0; kk < 4; kk++) {
                int base = rowq * qp32 + kk * 8 + tg;
                qfh[kk][0] = Qh32[base];
                qfh[kk][1] = Qh32[base + 8 * qp32];
                qfh[kk][2] = Qh32[base + 4];
                qfh[kk][3] = Qh32[base + 8 * qp32 + 4];
                qfl[kk][0] = Ql32[base];
                qfl[kk][1] = Ql32[base + 8 * qp32];
                qfl[kk][2] = Ql32[base + 4];
                qfl[kk][3] = Ql32[base + 8 * qp32 + 4];
            }
        }

        float m0 = -1e30f, m1 = -1e30f, l0s = 0.f, l1s = 0.f;
        float o[8][4];
#pragma unroll
        for (int nt = 0; nt < 8; nt++)
#pragma unroll
            for (int r = 0; r < 4; r++) o[nt][r] = 0.f;

        const int gr0 = q0 + warp * 16 + g;
        const int gr1 = gr0 + 8;

#pragma unroll 1
        for (int kt = 0; kt <= qt; kt++) {
            const int k0 = kt * 64;
            __syncthreads();
            // ---- fill K tile hi/lo ----
#pragma unroll
            for (int l = 0; l < 8; l++) {
                int idx = tid + l * 128;
                int r   = idx >> 4;
                int c   = (idx & 15) << 2;
                float4 v = *(const float4*)&Kg[(k0 + r) * HDIM + c];
                __nv_bfloat16 h0,l0,h1,l1,h2,l2,h3,l3;
                split2(v.x, h0, l0); split2(v.y, h1, l1);
                split2(v.z, h2, l2); split2(v.w, h3, l3);
                *(__nv_bfloat162*)&Kh[r*QKP + c]     = __halves2bfloat162(h0, h1);
                *(__nv_bfloat162*)&Kh[r*QKP + c + 2] = __halves2bfloat162(h2, h3);
                *(__nv_bfloat162*)&Kl[r*QKP + c]     = __halves2bfloat162(l0, l1);
                *(__nv_bfloat162*)&Kl[r*QKP + c + 2] = __halves2bfloat162(l2, l3);
            }
            // ---- fill V tile, k-pair packed ----
#pragma unroll
            for (int l = 0; l < 16; l++) {
                int idx = tid + l * 128;      // 0..2047
                int kp  = idx >> 6;
                int h   = idx & 63;
                float v0 = Vg[(k0 + 2 * kp)     * HDIM + h];
                float v1 = Vg[(k0 + 2 * kp + 1) * HDIM + h];
                uint32_t hp, lp;
                split_pack(v0, v1, hp, lp);
                Vh[kp * VPP + h] = hp;
                Vl[kp * VPP + h] = lp;
            }
            __syncthreads();

            // ---- S = Q K^T ----
            float s[8][4];
#pragma unroll
            for (int nt = 0; nt < 8; nt++)
#pragma unroll
                for (int r = 0; r < 4; r++) s[nt][r] = 0.f;

#pragma unroll
            for (int kk = 0; kk < 4; kk++) {
#pragma unroll
                for (int nt = 0; nt < 8; nt++) {
                    int base = (nt * 8 + g) * qp32 + kk * 8 + tg;
                    uint32_t bh0 = Kh32[base], bh1 = Kh32[base + 4];
                    uint32_t bl0 = Kl32[base], bl1 = Kl32[base + 4];
                    float* c = s[nt];
                    mma_bf16(c[0], c[1], c[2], c[3], qfh[kk][0], qfh[kk][1], qfh[kk][2], qfh[kk][3], bh0, bh1);
                    mma_bf16(c[0], c[1], c[2], c[3], qfl[kk][0], qfl[kk][1], qfl[kk][2], qfl[kk][3], bh0, bh1);
                    mma_bf16(c[0], c[1], c[2], c[3], qfh[kk][0], qfh[kk][1], qfh[kk][2], qfh[kk][3], bl0, bl1);
                }
            }

            // ---- scale (+ causal mask on diagonal tile), base-2 domain ----
            if (kt == qt) {
#pragma unroll
                for (int nt = 0; nt < 8; nt++) {
                    int c0 = k0 + nt * 8 + 2 * tg;
                    s[nt][0] = (c0     > gr0) ? -1e30f : s[nt][0] * C;
                    s[nt][1] = (c0 + 1 > gr0) ? -1e30f : s[nt][1] * C;
                    s[nt][2] = (c0     > gr1) ? -1e30f : s[nt][2] * C;
                    s[nt][3] = (c0 + 1 > gr1) ? -1e30f : s[nt][3] * C;
                }
            } else {
#pragma unroll
                for (int nt = 0; nt < 8; nt++)
#pragma unroll
                    for (int r = 0; r < 4; r++) s[nt][r] *= C;
            }

            // ---- online softmax (rows gr0 via s[.][0,1], gr1 via s[.][2,3]) ----
            float mA = -1e30f, mB = -1e30f;
#pragma unroll
            for (int nt = 0; nt < 8; nt++) {
                mA = fmaxf(mA, fmaxf(s[nt][0], s[nt][1]));
                mB = fmaxf(mB, fmaxf(s[nt][2], s[nt][3]));
            }
            mA = fmaxf(mA, __shfl_xor_sync(0xffffffffu, mA, 1));
            mA = fmaxf(mA, __shfl_xor_sync(0xffffffffu, mA, 2));
            mB = fmaxf(mB, __shfl_xor_sync(0xffffffffu, mB, 1));
            mB = fmaxf(mB, __shfl_xor_sync(0xffffffffu, mB, 2));
            float mn0 = fmaxf(m0, mA);
            float mn1 = fmaxf(m1, mB);
            float al0 = exp2f(m0 - mn0);
            float al1 = exp2f(m1 - mn1);
            m0 = mn0; m1 = mn1;

            uint32_t ph01[8], ph23[8], pl01[8], pl23[8];
            float rs0 = 0.f, rs1 = 0.f;
#pragma unroll
            for (int nt = 0; nt < 8; nt++) {
                float p0 = exp2f(s[nt][0] - mn0);
                float p1 = exp2f(s[nt][1] - mn0);
                float p2 = exp2f(s[nt][2] - mn1);
                float p3 = exp2f(s[nt][3] - mn1);
                rs0 += p0 + p1;
                rs1 += p2 + p3;
                split_pack(p0, p1, ph01[nt], pl01[nt]);
                split_pack(p2, p3, ph23[nt], pl23[nt]);
            }
            rs0 += __shfl_xor_sync(0xffffffffu, rs0, 1);
            rs0 += __shfl_xor_sync(0xffffffffu, rs0, 2);
            rs1 += __shfl_xor_sync(0xffffffffu, rs1, 1);
            rs1 += __shfl_xor_sync(0xffffffffu, rs1, 2);
            l0s = l0s * al0 + rs0;
            l1s = l1s * al1 + rs1;

#pragma unroll
            for (int nt = 0; nt < 8; nt++) {
                o[nt][0] *= al0; o[nt][1] *= al0;
                o[nt][2] *= al1; o[nt][3] *= al1;
            }

            // ---- O += P V ----
#pragma unroll
            for (int kk = 0; kk < 4; kk++) {
                uint32_t ah0 = ph01[2*kk],   ah1 = ph23[2*kk];
                uint32_t ah2 = ph01[2*kk+1], ah3 = ph23[2*kk+1];
                uint32_t al0_ = pl01[2*kk],   al1_ = pl23[2*kk];
                uint32_t al2_ = pl01[2*kk+1], al3_ = pl23[2*kk+1];
#pragma unroll
                for (int nt = 0; nt < 8; nt++) {
                    int h = nt * 8 + g;
                    uint32_t vb0h = Vh[(kk * 8 + tg) * VPP + h];
                    uint32_t vb1h = Vh[(kk * 8 + 4 + tg) * VPP + h];
                    uint32_t vb0l = Vl[(kk * 8 + tg) * VPP + h];
                    uint32_t vb1l = Vl[(kk * 8 + 4 + tg) * VPP + h];
                    float* c = o[nt];
                    mma_bf16(c[0], c[1], c[2], c[3], ah0, ah1, ah2, ah3, vb0h, vb1h);
                    mma_bf16(c[0], c[1], c[2], c[3], al0_, al1_, al2_, al3_, vb0h, vb1h);
                    mma_bf16(c[0], c[1], c[2], c[3], ah0, ah1, ah2, ah3, vb0l, vb1l);
                }
            }
        }

        // ---- epilogue ----
        float inv0 = 1.f / l0s;
        float inv1 = 1.f / l1s;
        size_t ro0 = ((size_t)b * SEQ + gr0) * HDIM;
        size_t ro1 = ((size_t)b * SEQ + gr1) * HDIM;
#pragma unroll
        for (int nt = 0; nt < 8; nt++) {
            int c = nt * 8 + 2 * tg;
            *(float2*)&out[ro0 + c] = make_float2(o[nt][0] * inv0, o[nt][1] * inv0);
            *(float2*)&out[ro1 + c] = make_float2(o[nt][2] * inv1, o[nt][3] * inv1);
        }
    }
}

// ---------------------------------------------------------------------------
extern "C" void kernel_launch(void* const* d_in, const int* in_sizes, int n_in,
                              void* d_out, int out_size)
{
    const float* x  = (const float*)d_in[0];
    const float* wk = (const float*)d_in[1];
    const float* wq = (const float*)d_in[2];
    const float* wv = (const float*)d_in[3];
    float* out = (float*)d_out;

    proj_kernel<<<MTOT / 128, 256>>>(x, wk, wq, wv);

    cudaFuncSetAttribute(attn_kernel,
                         cudaFuncAttributeMaxDynamicSharedMemorySize, ATTN_SMEM);
    dim3 grid(16, BATCH);
    attn_kernel<<<grid, 128, ATTN_SMEM>>>(out);
}

// round 3
// speedup vs baseline: 3.9155x; 1.5185x over previous
#include <cuda_runtime.h>
#include <cuda_bf16.h>
#include <stdint.h>

#define BATCH 8
#define SEQ   2048
#define EDIM  1024
#define HDIM  64
#define MTOT  (BATCH*SEQ)

// scratch (device globals: no allocation allowed)
__device__ float          g_v  [MTOT*HDIM];
__device__ __nv_bfloat16  g_qh [MTOT*HDIM], g_ql [MTOT*HDIM];
__device__ __nv_bfloat16  g_kh [MTOT*HDIM], g_kl [MTOT*HDIM];
__device__ uint32_t       g_vph[(MTOT/2)*HDIM], g_vpl[(MTOT/2)*HDIM];
__device__ uint32_t       g_wph[512*192],       g_wpl[512*192];

// ---------------------------------------------------------------------------
// helpers
// ---------------------------------------------------------------------------
__device__ __forceinline__ void mma_bf16(float& d0, float& d1, float& d2, float& d3,
                                         uint32_t a0, uint32_t a1, uint32_t a2, uint32_t a3,
                                         uint32_t b0, uint32_t b1)
{
    asm("mma.sync.aligned.m16n8k16.row.col.f32.bf16.bf16.f32 "
        "{%0,%1,%2,%3},{%4,%5,%6,%7},{%8,%9},{%0,%1,%2,%3};"
        : "+f"(d0), "+f"(d1), "+f"(d2), "+f"(d3)
        : "r"(a0), "r"(a1), "r"(a2), "r"(a3), "r"(b0), "r"(b1));
}

__device__ __forceinline__ void split2(float x, __nv_bfloat16& h, __nv_bfloat16& l)
{
    h = __float2bfloat16(x);
    l = __float2bfloat16(x - __bfloat162float(h));
}

__device__ __forceinline__ void split_pack(float x0, float x1, uint32_t& hp, uint32_t& lp)
{
    __nv_bfloat16 h0, l0, h1, l1;
    split2(x0, h0, l0);
    split2(x1, h1, l1);
    __nv_bfloat162 hh = __halves2bfloat162(h0, h1);
    __nv_bfloat162 ll = __halves2bfloat162(l0, l1);
    hp = *reinterpret_cast<uint32_t*>(&hh);
    lp = *reinterpret_cast<uint32_t*>(&ll);
}

__device__ __forceinline__ void cp16(uint32_t dst, const void* src)
{
    asm volatile("cp.async.cg.shared.global [%0], [%1], 16;" :: "r"(dst), "l"(src));
}
__device__ __forceinline__ uint32_t smem_u32(const void* p)
{
    uint32_t a;
    asm("{ .reg .u64 t; cvta.to.shared.u64 t, %1; cvt.u32.u64 %0, t; }" : "=r"(a) : "l"(p));
    return a;
}

// ---------------------------------------------------------------------------
// prep kernels: pack W (k-pair hi/lo u32) and V (k-pair hi/lo u32)
// ---------------------------------------------------------------------------
__global__ void prep_w(const float* __restrict__ wk, const float* __restrict__ wq,
                       const float* __restrict__ wv)
{
    int idx = blockIdx.x * 256 + threadIdx.x;       // 512*192 = 98304
    int kp = idx / 192, c = idx - kp * 192;
    const float* wp = (c < 64) ? wk : ((c < 128) ? wq : wv);
    int cc = c & 63;
    float w0 = wp[(2 * kp)     * HDIM + cc];
    float w1 = wp[(2 * kp + 1) * HDIM + cc];
    uint32_t hp, lp;
    split_pack(w0, w1, hp, lp);
    g_wph[idx] = hp;
    g_wpl[idx] = lp;
}

__global__ void prep_v()
{
    int idx = blockIdx.x * 256 + threadIdx.x;       // (MTOT/2)*64 = 524288
    int kp = idx >> 6, h = idx & 63;
    float v0 = g_v[(2 * kp)     * HDIM + h];
    float v1 = g_v[(2 * kp + 1) * HDIM + h];
    uint32_t hp, lp;
    split_pack(v0, v1, hp, lp);
    g_vph[idx] = hp;
    g_vpl[idx] = lp;
}

// ---------------------------------------------------------------------------
// Kernel 1: fused QKV projection, HMMA bf16 split, double-buffered.
// Block: 128 rows x 192 cols, 256 thr (8 warps = 2m x 4n), K-chunk 32.
// X: LDG prefetch -> split -> STS (double buffer). W: cp.async (prepacked).
// ---------------------------------------------------------------------------
#define AP   40         // X smem pitch (bf16)
#define BP   200        // W smem pitch (u32): bank = 8*tg + g, conflict-free
#define XH_OFF 0        // 2 x 10240
#define XL_OFF 20480
#define WH_OFF 40960    // 2 x 12800
#define WL_OFF 66560
#define PROJ_SMEM 92160

__global__ void __launch_bounds__(256) proj_kernel(const float* __restrict__ x)
{
    extern __shared__ unsigned char sm[];
    const uint32_t smb = smem_u32(sm);

    const int tid   = threadIdx.x;
    const int lane  = tid & 31;
    const int warp  = tid >> 5;
    const int warpM = warp >> 2;
    const int warpN = warp & 3;
    const int g     = lane >> 2;
    const int tg    = lane & 3;
    const int row0  = blockIdx.x * 128;

    float acc[4][6][4];
#pragma unroll
    for (int i = 0; i < 4; i++)
#pragma unroll
        for (int j = 0; j < 6; j++)
#pragma unroll
            for (int r = 0; r < 4; r++) acc[i][j][r] = 0.f;

    // X LDG target regs + index precompute
    float4 xr[4];
    int xrr[4], xcc[4];
#pragma unroll
    for (int l = 0; l < 4; l++) {
        int idx = tid + l * 256;
        xrr[l] = idx >> 3;
        xcc[l] = (idx & 7) << 2;
    }

    // ---- prologue: chunk 0 ----
#pragma unroll
    for (int l = 0; l < 4; l++)
        xr[l] = *(const float4*)&x[(size_t)(row0 + xrr[l]) * EDIM + xcc[l]];
    {
        __nv_bfloat16* XH = (__nv_bfloat16*)(sm + XH_OFF);
        __nv_bfloat16* XL = (__nv_bfloat16*)(sm + XL_OFF);
#pragma unroll
        for (int l = 0; l < 4; l++) {
            __nv_bfloat16 h0,l0,h1,l1,h2,l2,h3,l3;
            split2(xr[l].x, h0, l0); split2(xr[l].y, h1, l1);
            split2(xr[l].z, h2, l2); split2(xr[l].w, h3, l3);
            int base = xrr[l] * AP + xcc[l];
            *(__nv_bfloat162*)&XH[base]     = __halves2bfloat162(h0, h1);
            *(__nv_bfloat162*)&XH[base + 2] = __halves2bfloat162(h2, h3);
            *(__nv_bfloat162*)&XL[base]     = __halves2bfloat162(l0, l1);
            *(__nv_bfloat162*)&XL[base + 2] = __halves2bfloat162(l2, l3);
        }
    }
#pragma unroll
    for (int i = 0; i < 3; i++) {       // W chunk 0: 768 chunks x2 arrays
        int idx = tid + i * 256;
        int r   = idx / 48;
        int cc  = idx - r * 48;
        cp16(smb + WH_OFF + r * (BP*4) + cc * 16, (const char*)(g_wph + (size_t)r * 192) + cc * 16);
        cp16(smb + WL_OFF + r * (BP*4) + cc * 16, (const char*)(g_wpl + (size_t)r * 192) + cc * 16);
    }
    asm volatile("cp.async.commit_group;" ::: "memory");

#pragma unroll 1
    for (int k = 0; k < 32; k++) {
        const int buf = k & 1;
        if (k < 31) {
            const int k0n = (k + 1) * 32;
#pragma unroll
            for (int l = 0; l < 4; l++)
                xr[l] = *(const float4*)&x[(size_t)(row0 + xrr[l]) * EDIM + k0n + xcc[l]];
            const int kp0 = k0n >> 1;
            const uint32_t wdst = smb + ((k + 1) & 1) * 12800;
#pragma unroll
            for (int i = 0; i < 3; i++) {
                int idx = tid + i * 256;
                int r   = idx / 48;
                int cc  = idx - r * 48;
                cp16(wdst + WH_OFF + r * (BP*4) + cc * 16, (const char*)(g_wph + (size_t)(kp0 + r) * 192) + cc * 16);
                cp16(wdst + WL_OFF + r * (BP*4) + cc * 16, (const char*)(g_wpl + (size_t)(kp0 + r) * 192) + cc * 16);
            }
            asm volatile("cp.async.commit_group;" ::: "memory");
            asm volatile("cp.async.wait_group 1;" ::: "memory");
        } else {
            asm volatile("cp.async.wait_group 0;" ::: "memory");
        }
        __syncthreads();

        // ---- compute chunk k ----
        const uint32_t* Ah32 = (const uint32_t*)(sm + XH_OFF + buf * 10240);
        const uint32_t* Al32 = (const uint32_t*)(sm + XL_OFF + buf * 10240);
        const uint32_t* Bh   = (const uint32_t*)(sm + WH_OFF + buf * 12800);
        const uint32_t* Bl   = (const uint32_t*)(sm + WL_OFF + buf * 12800);
        const int ap32 = AP / 2;    // 20

#pragma unroll
        for (int k16 = 0; k16 < 2; k16++) {
            uint32_t ah[4][4], al[4][4];
#pragma unroll
            for (int mt = 0; mt < 4; mt++) {
                int rb = (warpM * 64 + mt * 16 + g) * ap32 + k16 * 8 + tg;
                ah[mt][0] = Ah32[rb];
                ah[mt][1] = Ah32[rb + 8 * ap32];
                ah[mt][2] = Ah32[rb + 4];
                ah[mt][3] = Ah32[rb + 8 * ap32 + 4];
                al[mt][0] = Al32[rb];
                al[mt][1] = Al32[rb + 8 * ap32];
                al[mt][2] = Al32[rb + 4];
                al[mt][3] = Al32[rb + 8 * ap32 + 4];
            }
#pragma unroll
            for (int nt = 0; nt < 6; nt++) {
                int n  = warpN * 48 + nt * 8 + g;
                int kp = k16 * 8 + tg;
                uint32_t bh0 = Bh[kp * BP + n], bh1 = Bh[(kp + 4) * BP + n];
                uint32_t bl0 = Bl[kp * BP + n], bl1 = Bl[(kp + 4) * BP + n];
#pragma unroll
                for (int mt = 0; mt < 4; mt++) {
                    float* c = acc[mt][nt];
                    mma_bf16(c[0], c[1], c[2], c[3], ah[mt][0], ah[mt][1], ah[mt][2], ah[mt][3], bh0, bh1);
                    mma_bf16(c[0], c[1], c[2], c[3], al[mt][0], al[mt][1], al[mt][2], al[mt][3], bh0, bh1);
                    mma_bf16(c[0], c[1], c[2], c[3], ah[mt][0], ah[mt][1], ah[mt][2], ah[mt][3], bl0, bl1);
                }
            }
        }

        // ---- stage X(k+1) into other buffer ----
        if (k < 31) {
            __nv_bfloat16* XH = (__nv_bfloat16*)(sm + XH_OFF + ((k + 1) & 1) * 10240);
            __nv_bfloat16* XL = (__nv_bfloat16*)(sm + XL_OFF + ((k + 1) & 1) * 10240);
#pragma unroll
            for (int l = 0; l < 4; l++) {
                __nv_bfloat16 h0,l0,h1,l1,h2,l2,h3,l3;
                split2(xr[l].x, h0, l0); split2(xr[l].y, h1, l1);
                split2(xr[l].z, h2, l2); split2(xr[l].w, h3, l3);
                int base = xrr[l] * AP + xcc[l];
                *(__nv_bfloat162*)&XH[base]     = __halves2bfloat162(h0, h1);
                *(__nv_bfloat162*)&XH[base + 2] = __halves2bfloat162(h2, h3);
                *(__nv_bfloat162*)&XL[base]     = __halves2bfloat162(l0, l1);
                *(__nv_bfloat162*)&XL[base + 2] = __halves2bfloat162(l2, l3);
            }
        }
        __syncthreads();
    }

    // ---- epilogue: K/Q as hi/lo bf16, V as float ----
    uint32_t* qh32 = (uint32_t*)g_qh; uint32_t* ql32 = (uint32_t*)g_ql;
    uint32_t* kh32 = (uint32_t*)g_kh; uint32_t* kl32 = (uint32_t*)g_kl;
#pragma unroll
    for (int mt = 0; mt < 4; mt++) {
#pragma unroll
        for (int nt = 0; nt < 6; nt++) {
            int gcol = warpN * 48 + nt * 8 + 2 * tg;
            int seg  = gcol >> 6;
            int cc   = gcol & 63;
            int r0   = row0 + warpM * 64 + mt * 16 + g;
            float* c = acc[mt][nt];
            if (seg == 2) {
                *(float2*)&g_v[r0 * HDIM + cc]       = make_float2(c[0], c[1]);
                *(float2*)&g_v[(r0 + 8) * HDIM + cc] = make_float2(c[2], c[3]);
            } else {
                uint32_t* dh = seg ? qh32 : kh32;
                uint32_t* dl = seg ? ql32 : kl32;
                uint32_t hp, lp;
                split_pack(c[0], c[1], hp, lp);
                dh[r0 * 32 + cc / 2] = hp;
                dl[r0 * 32 + cc / 2] = lp;
                split_pack(c[2], c[3], hp, lp);
                dh[(r0 + 8) * 32 + cc / 2] = hp;
                dl[(r0 + 8) * 32 + cc / 2] = lp;
            }
        }
    }
}

// ---------------------------------------------------------------------------
// Kernel 2: causal flash attention, 2 warp-groups per block.
// Group gw handles q-tile (gw ? p : 31-p). Private double-buffered K/V smem,
// cp.async fills, named barriers. Q fragments loaded directly from global.
// ---------------------------------------------------------------------------
#define KP32  36                        // K smem pitch (u32)
#define VPP   68                        // V smem pitch (u32)
#define ST_K   0                        // Kh at 0 (64*144 = 9216B), Kl at 9216
#define ST_V   18432                    // Vph (32*272 = 8704B), Vpl at 27136
#define STAGE  35840
#define GRP    (2*STAGE)                // 71680
#define ATTN_SMEM (2*GRP)               // 143360

__device__ __forceinline__ void fill_stage(uint32_t sb, int t, int k0,
                                           const __nv_bfloat16* kh, const __nv_bfloat16* kl,
                                           const uint32_t* vph, const uint32_t* vpl)
{
    const int kp0 = k0 >> 1;
#pragma unroll
    for (int i = 0; i < 4; i++) {
        int idx = t + i * 128;
        int r   = idx >> 3;
        int cc  = (idx & 7) * 16;
        cp16(sb + r * 144 + cc,        (const char*)(kh + (size_t)(k0 + r) * HDIM) + cc);
        cp16(sb + 9216 + r * 144 + cc, (const char*)(kl + (size_t)(k0 + r) * HDIM) + cc);
    }
#pragma unroll
    for (int i = 0; i < 4; i++) {
        int idx = t + i * 128;
        int r   = idx >> 4;
        int cc  = (idx & 15) * 16;
        cp16(sb + ST_V + r * 272 + cc,        (const char*)(vph + (size_t)(kp0 + r) * HDIM) + cc);
        cp16(sb + ST_V + 8704 + r * 272 + cc, (const char*)(vpl + (size_t)(kp0 + r) * HDIM) + cc);
    }
}

__global__ void __launch_bounds__(256) attn_kernel(float* __restrict__ out)
{
    extern __shared__ unsigned char smraw[];

    const int tid  = threadIdx.x;
    const int lane = tid & 31;
    const int warp = tid >> 5;
    const int gw   = warp >> 2;        // warp-group 0/1
    const int wi   = warp & 3;
    const int t    = tid & 127;
    const int g    = lane >> 2;
    const int tg   = lane & 3;
    const int p    = blockIdx.x;       // 0..15
    const int b    = blockIdx.y;

    const int qt = gw ? p : (31 - p);
    const int q0 = qt * 64;

    const __nv_bfloat16* Khg  = g_kh  + (size_t)b * SEQ * HDIM;
    const __nv_bfloat16* Klg  = g_kl  + (size_t)b * SEQ * HDIM;
    const uint32_t*      Vphg = g_vph + (size_t)b * (SEQ/2) * HDIM;
    const uint32_t*      Vplg = g_vpl + (size_t)b * (SEQ/2) * HDIM;
    const uint32_t*      qh32 = (const uint32_t*)g_qh + (size_t)b * SEQ * 32;
    const uint32_t*      ql32 = (const uint32_t*)g_ql + (size_t)b * SEQ * 32;

    const uint32_t gb   = smem_u32(smraw) + gw * GRP;
    const unsigned char* gsm = smraw + gw * GRP;

    // ---- Q fragments from global ----
    const int rowq = wi * 16 + g;
    uint32_t qfh[4][4], qfl[4][4];
    {
        int base = (q0 + rowq) * 32;
#pragma unroll
        for (int kk = 0; kk < 4; kk++) {
            int o0 = base + kk * 8 + tg;
            qfh[kk][0] = qh32[o0];
            qfh[kk][1] = qh32[o0 + 8 * 32];
            qfh[kk][2] = qh32[o0 + 4];
            qfh[kk][3] = qh32[o0 + 8 * 32 + 4];
            qfl[kk][0] = ql32[o0];
            qfl[kk][1] = ql32[o0 + 8 * 32];
            qfl[kk][2] = ql32[o0 + 4];
            qfl[kk][3] = ql32[o0 + 8 * 32 + 4];
        }
    }

    // ---- prologue fills ----
    fill_stage(gb, t, 0, Khg, Klg, Vphg, Vplg);
    asm volatile("cp.async.commit_group;" ::: "memory");
    if (qt >= 1) {
        fill_stage(gb + STAGE, t, 64, Khg, Klg, Vphg, Vplg);
        asm volatile("cp.async.commit_group;" ::: "memory");
    }

    float m0 = -1e30f, m1 = -1e30f, l0s = 0.f, l1s = 0.f;
    float o[8][4];
#pragma unroll
    for (int nt = 0; nt < 8; nt++)
#pragma unroll
        for (int r = 0; r < 4; r++) o[nt][r] = 0.f;

    const int gr0 = q0 + rowq;
    const int gr1 = gr0 + 8;
    const float C = 0.125f * 1.44269504088896340736f;   // scale * log2(e)
    const int barid = gw + 1;

#pragma unroll 1
    for (int kt = 0; kt <= qt; kt++) {
        if (kt >= 1 && kt < qt) {
            fill_stage(gb + ((kt + 1) & 1) * STAGE, t, (kt + 1) * 64, Khg, Klg, Vphg, Vplg);
            asm volatile("cp.async.commit_group;" ::: "memory");
        }
        if (kt < qt) asm volatile("cp.async.wait_group 1;" ::: "memory");
        else         asm volatile("cp.async.wait_group 0;" ::: "memory");
        asm volatile("bar.sync %0, 128;" :: "r"(barid) : "memory");

        const int sbuf = (kt & 1) * STAGE;
        const uint32_t* KH32 = (const uint32_t*)(gsm + sbuf);
        const uint32_t* KL32 = (const uint32_t*)(gsm + sbuf + 9216);
        const uint32_t* VPH  = (const uint32_t*)(gsm + sbuf + ST_V);
        const uint32_t* VPL  = (const uint32_t*)(gsm + sbuf + ST_V + 8704);
        const int k0 = kt * 64;

        // ---- S = Q K^T ----
        float s[8][4];
#pragma unroll
        for (int nt = 0; nt < 8; nt++)
#pragma unroll
            for (int r = 0; r < 4; r++) s[nt][r] = 0.f;

#pragma unroll
        for (int kk = 0; kk < 4; kk++) {
#pragma unroll
            for (int nt = 0; nt < 8; nt++) {
                int base = (nt * 8 + g) * KP32 + kk * 8 + tg;
                uint32_t bh0 = KH32[base], bh1 = KH32[base + 4];
                uint32_t bl0 = KL32[base], bl1 = KL32[base + 4];
                float* c = s[nt];
                mma_bf16(c[0], c[1], c[2], c[3], qfh[kk][0], qfh[kk][1], qfh[kk][2], qfh[kk][3], bh0, bh1);
                mma_bf16(c[0], c[1], c[2], c[3], qfl[kk][0], qfl[kk][1], qfl[kk][2], qfl[kk][3], bh0, bh1);
                mma_bf16(c[0], c[1], c[2], c[3], qfh[kk][0], qfh[kk][1], qfh[kk][2], qfh[kk][3], bl0, bl1);
            }
        }

        // ---- scale + causal mask (diagonal tile only) ----
        if (kt == qt) {
#pragma unroll
            for (int nt = 0; nt < 8; nt++) {
                int c0 = k0 + nt * 8 + 2 * tg;
                s[nt][0] = (c0     > gr0) ? -1e30f : s[nt][0] * C;
                s[nt][1] = (c0 + 1 > gr0) ? -1e30f : s[nt][1] * C;
                s[nt][2] = (c0     > gr1) ? -1e30f : s[nt][2] * C;
                s[nt][3] = (c0 + 1 > gr1) ? -1e30f : s[nt][3] * C;
            }
        } else {
#pragma unroll
            for (int nt = 0; nt < 8; nt++)
#pragma unroll
                for (int r = 0; r < 4; r++) s[nt][r] *= C;
        }

        // ---- online softmax ----
        float mA = -1e30f, mB = -1e30f;
#pragma unroll
        for (int nt = 0; nt < 8; nt++) {
            mA = fmaxf(mA, fmaxf(s[nt][0], s[nt][1]));
            mB = fmaxf(mB, fmaxf(s[nt][2], s[nt][3]));
        }
        mA = fmaxf(mA, __shfl_xor_sync(0xffffffffu, mA, 1));
        mA = fmaxf(mA, __shfl_xor_sync(0xffffffffu, mA, 2));
        mB = fmaxf(mB, __shfl_xor_sync(0xffffffffu, mB, 1));
        mB = fmaxf(mB, __shfl_xor_sync(0xffffffffu, mB, 2));
        float mn0 = fmaxf(m0, mA);
        float mn1 = fmaxf(m1, mB);
        float al0 = exp2f(m0 - mn0);
        float al1 = exp2f(m1 - mn1);
        m0 = mn0; m1 = mn1;

        uint32_t ph01[8], ph23[8], pl01[8], pl23[8];
        float rs0 = 0.f, rs1 = 0.f;
#pragma unroll
        for (int nt = 0; nt < 8; nt++) {
            float p0 = exp2f(s[nt][0] - mn0);
            float p1 = exp2f(s[nt][1] - mn0);
            float p2 = exp2f(s[nt][2] - mn1);
            float p3 = exp2f(s[nt][3] - mn1);
            rs0 += p0 + p1;
            rs1 += p2 + p3;
            split_pack(p0, p1, ph01[nt], pl01[nt]);
            split_pack(p2, p3, ph23[nt], pl23[nt]);
        }
        rs0 += __shfl_xor_sync(0xffffffffu, rs0, 1);
        rs0 += __shfl_xor_sync(0xffffffffu, rs0, 2);
        rs1 += __shfl_xor_sync(0xffffffffu, rs1, 1);
        rs1 += __shfl_xor_sync(0xffffffffu, rs1, 2);
        l0s = l0s * al0 + rs0;
        l1s = l1s * al1 + rs1;

#pragma unroll
        for (int nt = 0; nt < 8; nt++) {
            o[nt][0] *= al0; o[nt][1] *= al0;
            o[nt][2] *= al1; o[nt][3] *= al1;
        }

        // ---- O += P V ----
#pragma unroll
        for (int kk = 0; kk < 4; kk++) {
            uint32_t ah0 = ph01[2*kk],   ah1 = ph23[2*kk];
            uint32_t ah2 = ph01[2*kk+1], ah3 = ph23[2*kk+1];
            uint32_t aL0 = pl01[2*kk],   aL1 = pl23[2*kk];
            uint32_t aL2 = pl01[2*kk+1], aL3 = pl23[2*kk+1];
#pragma unroll
            for (int nt = 0; nt < 8; nt++) {
                int h = nt * 8 + g;
                uint32_t vb0h = VPH[(kk * 8 + tg) * VPP + h];
                uint32_t vb1h = VPH[(kk * 8 + 4 + tg) * VPP + h];
                uint32_t vb0l = VPL[(kk * 8 + tg) * VPP + h];
                uint32_t vb1l = VPL[(kk * 8 + 4 + tg) * VPP + h];
                float* c = o[nt];
                mma_bf16(c[0], c[1], c[2], c[3], ah0, ah1, ah2, ah3, vb0h, vb1h);
                mma_bf16(c[0], c[1], c[2], c[3], aL0, aL1, aL2, aL3, vb0h, vb1h);
                mma_bf16(c[0], c[1], c[2], c[3], ah0, ah1, ah2, ah3, vb0l, vb1l);
            }
        }
        asm volatile("bar.sync %0, 128;" :: "r"(barid) : "memory");
    }

    // ---- epilogue ----
    float inv0 = 1.f / l0s;
    float inv1 = 1.f / l1s;
    size_t ro0 = ((size_t)b * SEQ + gr0) * HDIM;
    size_t ro1 = ((size_t)b * SEQ + gr1) * HDIM;
#pragma unroll
    for (int nt = 0; nt < 8; nt++) {
        int c = nt * 8 + 2 * tg;
        *(float2*)&out[ro0 + c] = make_float2(o[nt][0] * inv0, o[nt][1] * inv0);
        *(float2*)&out[ro1 + c] = make_float2(o[nt][2] * inv1, o[nt][3] * inv1);
    }
}

// ---------------------------------------------------------------------------
extern "C" void kernel_launch(void* const* d_in, const int* in_sizes, int n_in,
                              void* d_out, int out_size)
{
    const float* x  = (const float*)d_in[0];
    const float* wk = (const float*)d_in[1];
    const float* wq = (const float*)d_in[2];
    const float* wv = (const float*)d_in[3];
    float* out = (float*)d_out;

    prep_w<<<384, 256>>>(wk, wq, wv);

    cudaFuncSetAttribute(proj_kernel,
                         cudaFuncAttributeMaxDynamicSharedMemorySize, PROJ_SMEM);
    proj_kernel<<<MTOT / 128, 256, PROJ_SMEM>>>(x);

    prep_v<<<2048, 256>>>();

    cudaFuncSetAttribute(attn_kernel,
                         cudaFuncAttributeMaxDynamicSharedMemorySize, ATTN_SMEM);
    dim3 grid(16, BATCH);
    attn_kernel<<<grid, 256, ATTN_SMEM>>>(out);
}